// round 9
// baseline (speedup 1.0000x reference)
#include <cuda_runtime.h>
#include <cstdint>

// LIF neuron scan: v = 0.5*v + x_t; spike = (v >= 1); v = spike ? 0 : v
// x: [T, B, D] f32, v0: [D] f32, out spikes: [T, B, D] f32.
//
// R9 = R8 (float2 chains, 148 CTAs x 256 thr, ~7 warps/SM, per-thread cp.async
// ring, no __syncthreads) with the ring DOUBLED to 48 stages (96 KB dynamic
// smem, 44-step slack) to cover L1tex/LTS tail-latency spikes that a 20-step
// slack exposes. Reads L2::evict_first; stores __stcs.

#define LIF_CTA    256
#define LIF_GRID   148
#define LIF_BATCH  4
#define LIF_GROUPS 12
#define LIF_STAGES (LIF_BATCH * LIF_GROUPS)   // 48 slots x 256 thr x 8B = 96 KB
#define LIF_SMEM   (LIF_STAGES * LIF_CTA * 8)
#define LIF_TAU    0.5f

__global__ void __launch_bounds__(LIF_CTA, 1)
lif_scan_kernel(const float* __restrict__ x,
                const float* __restrict__ v0,
                float* __restrict__ out,
                int T, int N2, int D2, int chunk)
{
    extern __shared__ float2 ring[];   // [LIF_STAGES][LIF_CTA]

    const int chain = blockIdx.x * chunk + threadIdx.x;
    if (threadIdx.x >= chunk || chain >= N2) return;

    uint32_t slot0 = (uint32_t)__cvta_generic_to_shared(&ring[threadIdx.x]);
    const uint32_t stage_bytes = LIF_CTA * 8u;

    const char* gp = (const char*)x + (size_t)chain * 8u;
    const size_t gstride = (size_t)N2 * 8u;      // bytes per timestep

    // L2 evict-first for the read-once input stream
    uint64_t pol_r;
    asm volatile("createpolicy.fractional.L2::evict_first.b64 %0, 1.0;\n"
                 : "=l"(pol_r));

    // ---- prologue: fill GROUPS-1 = 11 groups (44 stages) ----
    #pragma unroll
    for (int g = 0; g < LIF_GROUPS - 1; g++) {
        #pragma unroll
        for (int j = 0; j < LIF_BATCH; j++) {
            uint32_t dst = slot0 + (uint32_t)(g * LIF_BATCH + j) * stage_bytes;
            asm volatile(
                "cp.async.ca.shared.global.L2::cache_hint [%0], [%1], 8, %2;\n"
                :: "r"(dst), "l"(gp), "l"(pol_r) : "memory");
            gp += gstride;
        }
        asm volatile("cp.async.commit_group;\n" ::: "memory");
    }

    // initial membrane potential: v0[d] broadcast over batch
    float2 v = ((const float2*)v0)[chain % D2];

    float2* op = (float2*)out + chain;

    int wgrp = LIF_GROUPS - 1;   // ring group to write next
    int rslot = 0;               // stage slot to read next

    const int prefetched = (LIF_GROUPS - 1) * LIF_BATCH;   // 44 steps

    for (int t = 0; t < T; t += LIF_BATCH) {
        // issue group for steps t+44..t+47 (if any); ALWAYS commit one group
        // per iteration so positional wait_group accounting holds
        if (t + prefetched < T) {
            #pragma unroll
            for (int j = 0; j < LIF_BATCH; j++) {
                uint32_t dst = slot0 +
                    (uint32_t)(wgrp * LIF_BATCH + j) * stage_bytes;
                asm volatile(
                    "cp.async.ca.shared.global.L2::cache_hint [%0], [%1], 8, %2;\n"
                    :: "r"(dst), "l"(gp), "l"(pol_r) : "memory");
                gp += gstride;
            }
        }
        asm volatile("cp.async.commit_group;\n" ::: "memory");
        if (++wgrp == LIF_GROUPS) wgrp = 0;

        // all but the 11 most recent groups complete -> this batch landed
        asm volatile("cp.async.wait_group %0;\n" :: "n"(LIF_GROUPS - 1) : "memory");

        #pragma unroll
        for (int j = 0; j < LIF_BATCH; j++) {
            float2 xt;
            uint32_t src = slot0 + (uint32_t)rslot * stage_bytes;
            asm volatile("ld.shared.v2.f32 {%0,%1}, [%2];\n"
                         : "=f"(xt.x), "=f"(xt.y)
                         : "r"(src));
            if (++rslot == LIF_STAGES) rslot = 0;

            float2 sp;
            v.x = fmaf(LIF_TAU, v.x, xt.x);
            v.y = fmaf(LIF_TAU, v.y, xt.y);
            bool fx = v.x >= 1.0f, fy = v.y >= 1.0f;
            sp.x = fx ? 1.0f : 0.0f;  v.x = fx ? 0.0f : v.x;
            sp.y = fy ? 1.0f : 0.0f;  v.y = fy ? 0.0f : v.y;

            __stcs(op, sp);
            op += N2;
        }
    }
}

extern "C" void kernel_launch(void* const* d_in, const int* in_sizes, int n_in,
                              void* d_out, int out_size)
{
    const float* x  = (const float*)d_in[0];   // [T, B, D]
    const float* v0 = (const float*)d_in[1];   // [D]
    float* out = (float*)d_out;

    const int T = 512;                 // fixed by problem setup
    const int total = in_sizes[0];     // T*B*D
    const int D = in_sizes[1];
    const int N  = total / T;          // B*D
    const int N2 = N / 2;              // float2 chains
    const int D2 = D / 2;

    // opt in to 96 KB dynamic smem (host attribute set; no allocation)
    static bool attr_done = false;
    if (!attr_done) {
        cudaFuncSetAttribute(lif_scan_kernel,
                             cudaFuncAttributeMaxDynamicSharedMemorySize,
                             LIF_SMEM);
        attr_done = true;
    }

    // Spread chains over all 148 SMs; chains per CTA capped at CTA size.
    int chunk = (N2 + LIF_GRID - 1) / LIF_GRID;   // 222 for N2=32768
    if (chunk > LIF_CTA) chunk = LIF_CTA;
    int grid = (N2 + chunk - 1) / chunk;

    lif_scan_kernel<<<grid, LIF_CTA, LIF_SMEM>>>(x, v0, out, T, N2, D2, chunk);
}